// round 1
// baseline (speedup 1.0000x reference)
#include <cuda_runtime.h>
#include <math.h>

// ---------------- problem constants ----------------
#define NIMG   2
#define S_PER  512
#define R_TOT  1024          // NIMG * S_PER
#define C_FEAT 512
#define HW     2500          // 50*50
#define OUTSZ  7
#define D_FEAT 25088         // C_FEAT * 49
#define HIDN   1024
#define NCLS   21
#define DETN   100
#define CANDS  10240         // S_PER * (NCLS-1)
#define LOG_MAX_F 4.135166556742356f

// ---------------- scratch (static device memory, no allocation) ----------------
__device__ float  g_featT[NIMG * HW * C_FEAT];        // [n][y][x][c]  10.2 MB
__device__ float  g_feats[(size_t)R_TOT * D_FEAT];    // [r][c*49+pos] 102.8 MB
__device__ float  g_h1[R_TOT * HIDN];
__device__ float  g_h2[R_TOT * HIDN];
__device__ float  g_scores[R_TOT * NCLS];
__device__ float4 g_boxes4[R_TOT * NCLS];             // decoded, clipped boxes
__device__ float4 g_nb[NIMG * CANDS];                 // class-offset boxes
__device__ float  g_area[NIMG * CANDS];

// Robustly read image_size regardless of scalar dtype (int32/int64/f32/f64).
__device__ __forceinline__ float read_img(const void* p) {
    int iv = *(const int*)p;
    if (iv > 0 && iv < 1000000) return (float)iv;
    float fv = *(const float*)p;
    if (fv >= 1.0f && fv <= 1.0e6f) return fv;
    double dv = *(const double*)p;
    return (float)dv;
}

// ---------------- 1) transpose features [N,C,H,W] -> [N,H,W,C] ----------------
__global__ void transpose_feat(const float* __restrict__ in) {
    __shared__ float tile[32][33];
    int n  = blockIdx.z;
    int p0 = blockIdx.x * 32;  // spatial (hw)
    int c0 = blockIdx.y * 32;  // channel
    int tx = threadIdx.x, ty = threadIdx.y;
    int p = p0 + tx, c = c0 + ty;
    if (p < HW) tile[ty][tx] = in[((size_t)(n * C_FEAT + c)) * HW + p];
    __syncthreads();
    p = p0 + ty; c = c0 + tx;
    if (p < HW) g_featT[((size_t)(n * HW + p)) * C_FEAT + c] = tile[tx][ty];
}

// ---------------- 2) ROI align -> g_feats [r][c*49 + oy*7+ox] ----------------
__global__ void roi_align_kernel(const float* __restrict__ props) {
    int bid = blockIdx.x;
    int r   = bid / 49;
    int pos = bid % 49;
    int oy  = pos / 7, ox = pos % 7;
    int n   = r >> 9;                 // r / S_PER
    const float SCALE = 1.0f / 16.0f;
    float b0 = props[r*4+0] * SCALE;
    float b1 = props[r*4+1] * SCALE;
    float b2 = props[r*4+2] * SCALE;
    float b3 = props[r*4+3] * SCALE;
    float rw = fmaxf(b2 - b0, 1.0f);
    float rh = fmaxf(b3 - b1, 1.0f);
    float bw = rw * (1.0f / 7.0f);
    float bh = rh * (1.0f / 7.0f);

    int c0 = threadIdx.x * 4;         // 128 threads * 4 channels
    float4 acc = make_float4(0.f, 0.f, 0.f, 0.f);
    const float* base = g_featT + ((size_t)n * HW) * C_FEAT;

    #pragma unroll
    for (int sy = 0; sy < 2; sy++) {
        float gy = (float)oy + (sy ? 0.75f : 0.25f);
        float y  = b1 + gy * bh;
        bool  vy = (y > -1.0f) && (y < 50.0f);
        float yc = fminf(fmaxf(y, 0.0f), 49.0f);
        int   y0 = (int)floorf(yc);
        int   y1 = min(y0 + 1, 49);
        float ly = yc - (float)y0;
        #pragma unroll
        for (int sx = 0; sx < 2; sx++) {
            float gx = (float)ox + (sx ? 0.75f : 0.25f);
            float x  = b0 + gx * bw;
            bool  vx = (x > -1.0f) && (x < 50.0f);
            if (!(vy && vx)) continue;
            float xc = fminf(fmaxf(x, 0.0f), 49.0f);
            int   x0 = (int)floorf(xc);
            int   x1 = min(x0 + 1, 49);
            float lx = xc - (float)x0;
            const float4 f00 = *(const float4*)(base + ((size_t)(y0*50 + x0)) * C_FEAT + c0);
            const float4 f01 = *(const float4*)(base + ((size_t)(y0*50 + x1)) * C_FEAT + c0);
            const float4 f10 = *(const float4*)(base + ((size_t)(y1*50 + x0)) * C_FEAT + c0);
            const float4 f11 = *(const float4*)(base + ((size_t)(y1*50 + x1)) * C_FEAT + c0);
            float w00 = (1.0f-ly)*(1.0f-lx), w01 = (1.0f-ly)*lx;
            float w10 = ly*(1.0f-lx),        w11 = ly*lx;
            acc.x += f00.x*w00 + f01.x*w01 + f10.x*w10 + f11.x*w11;
            acc.y += f00.y*w00 + f01.y*w01 + f10.y*w10 + f11.y*w11;
            acc.z += f00.z*w00 + f01.z*w01 + f10.z*w10 + f11.z*w11;
            acc.w += f00.w*w00 + f01.w*w01 + f10.w*w10 + f11.w*w11;
        }
    }
    float* outp = g_feats + (size_t)r * D_FEAT + pos;
    outp[(size_t)(c0+0)*49] = acc.x * 0.25f;
    outp[(size_t)(c0+1)*49] = acc.y * 0.25f;
    outp[(size_t)(c0+2)*49] = acc.z * 0.25f;
    outp[(size_t)(c0+3)*49] = acc.w * 0.25f;
}

// ---------------- 3) GEMM: C = relu(A[MxK] @ B[KxN] + bias) ----------------
// 64x64 tile, BK=16, 256 threads, 4x4 per thread. M,N,K divisible by tile.
__global__ __launch_bounds__(256) void gemm_bias_relu(
    const float* __restrict__ A, const float* __restrict__ B,
    const float* __restrict__ bias, float* __restrict__ C,
    int M, int N, int K, int do_relu)
{
    __shared__ __align__(16) float As[16][68];
    __shared__ __align__(16) float Bs[16][64];
    int tid = threadIdx.x;
    int ty = tid >> 4, tx = tid & 15;
    int row0 = blockIdx.y * 64;
    int col0 = blockIdx.x * 64;

    int alm = tid >> 2;          // 0..63 : A tile row
    int alk = (tid & 3) * 4;     // 0,4,8,12 : A tile k
    int bkr = tid >> 4;          // 0..15 : B tile k
    int bnc = (tid & 15) * 4;    // 0..60 : B tile col

    const float* Ap = A + (size_t)(row0 + alm) * K + alk;
    const float* Bp = B + (size_t)bkr * N + col0 + bnc;

    float acc[4][4];
    #pragma unroll
    for (int i = 0; i < 4; i++)
        #pragma unroll
        for (int j = 0; j < 4; j++) acc[i][j] = 0.0f;

    for (int k0 = 0; k0 < K; k0 += 16) {
        float4 va = *(const float4*)(Ap + k0);
        float4 vb = *(const float4*)(Bp + (size_t)k0 * N);
        As[alk+0][alm] = va.x;
        As[alk+1][alm] = va.y;
        As[alk+2][alm] = va.z;
        As[alk+3][alm] = va.w;
        *(float4*)&Bs[bkr][bnc] = vb;
        __syncthreads();
        #pragma unroll
        for (int kk = 0; kk < 16; kk++) {
            float4 a = *(const float4*)&As[kk][ty*4];
            float4 b = *(const float4*)&Bs[kk][tx*4];
            float av[4] = {a.x, a.y, a.z, a.w};
            float bv[4] = {b.x, b.y, b.z, b.w};
            #pragma unroll
            for (int i = 0; i < 4; i++)
                #pragma unroll
                for (int j = 0; j < 4; j++)
                    acc[i][j] += av[i] * bv[j];
        }
        __syncthreads();
    }

    #pragma unroll
    for (int i = 0; i < 4; i++) {
        int rr = row0 + ty*4 + i;
        #pragma unroll
        for (int j = 0; j < 4; j++) {
            int cc = col0 + tx*4 + j;
            float v = acc[i][j] + bias[cc];
            if (do_relu) v = fmaxf(v, 0.0f);
            C[(size_t)rr * N + cc] = v;
        }
    }
}

// ---------------- 4) heads: cls/deltas GEMV + softmax + decode + clip ----------------
__global__ void heads_kernel(
    const float* __restrict__ wc, const float* __restrict__ bc,
    const float* __restrict__ wb, const float* __restrict__ bb,
    const float* __restrict__ props, const void* __restrict__ imgp)
{
    int r = blockIdx.x, tid = threadIdx.x;   // 128 threads
    __shared__ float h[HIDN];
    __shared__ float clsv[NCLS];
    __shared__ float dl[NCLS * 4];
    __shared__ float ex[NCLS];

    for (int i = tid; i < HIDN; i += 128) h[i] = g_h2[r * HIDN + i];
    __syncthreads();

    if (tid < NCLS) {
        float a0 = 0.f, a1 = 0.f, a2 = 0.f, a3 = 0.f;
        #pragma unroll 4
        for (int k = 0; k < HIDN; k += 4) {
            a0 += h[k+0] * wc[(k+0)*NCLS + tid];
            a1 += h[k+1] * wc[(k+1)*NCLS + tid];
            a2 += h[k+2] * wc[(k+2)*NCLS + tid];
            a3 += h[k+3] * wc[(k+3)*NCLS + tid];
        }
        clsv[tid] = (a0 + a1) + (a2 + a3) + bc[tid];
    } else if (tid < NCLS + 84) {
        int j = tid - NCLS;
        float a0 = 0.f, a1 = 0.f, a2 = 0.f, a3 = 0.f;
        #pragma unroll 4
        for (int k = 0; k < HIDN; k += 4) {
            a0 += h[k+0] * wb[(k+0)*84 + j];
            a1 += h[k+1] * wb[(k+1)*84 + j];
            a2 += h[k+2] * wb[(k+2)*84 + j];
            a3 += h[k+3] * wb[(k+3)*84 + j];
        }
        dl[j] = (a0 + a1) + (a2 + a3) + bb[j];
    }
    __syncthreads();

    if (tid < NCLS) {
        float m = clsv[0];
        #pragma unroll
        for (int i = 1; i < NCLS; i++) m = fmaxf(m, clsv[i]);
        ex[tid] = expf(clsv[tid] - m);
    }
    __syncthreads();

    if (tid < NCLS) {
        float s = 0.f;
        #pragma unroll
        for (int i = 0; i < NCLS; i++) s += ex[i];
        g_scores[r * NCLS + tid] = ex[tid] / s;

        float img = read_img(imgp);
        float p0 = props[r*4+0], p1 = props[r*4+1];
        float p2 = props[r*4+2], p3 = props[r*4+3];
        float pw  = p2 - p0, ph = p3 - p1;
        float pcx = p0 + 0.5f * pw, pcy = p1 + 0.5f * ph;
        float dx = dl[tid*4+0] / 10.0f;
        float dy = dl[tid*4+1] / 10.0f;
        float dw = fminf(dl[tid*4+2] / 5.0f, LOG_MAX_F);
        float dh = fminf(dl[tid*4+3] / 5.0f, LOG_MAX_F);
        float cx = dx * pw + pcx;
        float cy = dy * ph + pcy;
        float w  = expf(dw) * pw;
        float hh = expf(dh) * ph;
        float x1 = fminf(fmaxf(cx - 0.5f*w,  0.0f), img);
        float y1 = fminf(fmaxf(cy - 0.5f*hh, 0.0f), img);
        float x2 = fminf(fmaxf(cx + 0.5f*w,  0.0f), img);
        float y2 = fminf(fmaxf(cy + 0.5f*hh, 0.0f), img);
        g_boxes4[r * NCLS + tid] = make_float4(x1, y1, x2, y2);
    }
}

// ---------------- 5) exact sequential NMS, one block per image ----------------
__global__ __launch_bounds__(1024) void nms_kernel(const void* __restrict__ imgp,
                                                   float* __restrict__ out)
{
    int img = blockIdx.x;
    int tid = threadIdx.x;
    float IMG  = read_img(imgp);
    float offs = IMG + 1.0f;

    __shared__ float live[CANDS];
    __shared__ float wbest[32];
    __shared__ int   widx[32];
    __shared__ float selS[DETN];
    __shared__ int   selI[DETN];
    __shared__ int   s_si;

    // setup candidates
    #pragma unroll
    for (int g = 0; g < 10; g++) {
        int cand = g * 1024 + tid;
        int s = cand / 20, k = cand % 20 + 1;
        int r = img * S_PER + s;
        float sc  = g_scores[r * NCLS + k];
        float4 bx = g_boxes4[r * NCLS + k];
        float wv = bx.z - bx.x, hv = bx.w - bx.y;
        bool valid = (sc > 0.05f) && (wv >= 0.01f) && (hv >= 0.01f);
        live[cand] = valid ? sc : -1.0f;
        float o = (float)k * offs;
        float4 nb = make_float4(bx.x + o, bx.y + o, bx.z + o, bx.w + o);
        g_nb[img * CANDS + cand]   = nb;
        g_area[img * CANDS + cand] = (nb.z - nb.x) * (nb.w - nb.y);
    }
    __syncthreads();

    int lane = tid & 31, wid = tid >> 5;

    for (int it = 0; it < DETN; it++) {
        // argmax (first-index tie-break, matching jnp.argmax)
        float best = -2.0f; int bidx = CANDS;
        #pragma unroll
        for (int g = 0; g < 10; g++) {
            int cand = g * 1024 + tid;
            float v = live[cand];
            if (v > best) { best = v; bidx = cand; }
        }
        #pragma unroll
        for (int o = 16; o; o >>= 1) {
            float ov = __shfl_down_sync(0xffffffffu, best, o);
            int   oi = __shfl_down_sync(0xffffffffu, bidx, o);
            if (ov > best || (ov == best && oi < bidx)) { best = ov; bidx = oi; }
        }
        if (lane == 0) { wbest[wid] = best; widx[wid] = bidx; }
        __syncthreads();
        if (wid == 0) {
            best = wbest[lane]; bidx = widx[lane];
            #pragma unroll
            for (int o = 16; o; o >>= 1) {
                float ov = __shfl_down_sync(0xffffffffu, best, o);
                int   oi = __shfl_down_sync(0xffffffffu, bidx, o);
                if (ov > best || (ov == best && oi < bidx)) { best = ov; bidx = oi; }
            }
            if (lane == 0) { s_si = bidx; selI[it] = bidx; selS[it] = best; }
        }
        __syncthreads();

        int si = s_si;
        float4 nbb = g_nb[img * CANDS + si];
        float area_i = (nbb.z - nbb.x) * (nbb.w - nbb.y);
        #pragma unroll
        for (int g = 0; g < 10; g++) {
            int cand = g * 1024 + tid;
            float4 nb = g_nb[img * CANDS + cand];
            float xx1 = fmaxf(nbb.x, nb.x);
            float yy1 = fmaxf(nbb.y, nb.y);
            float xx2 = fminf(nbb.z, nb.z);
            float yy2 = fminf(nbb.w, nb.w);
            float inter = fmaxf(xx2 - xx1, 0.0f) * fmaxf(yy2 - yy1, 0.0f);
            float iou = inter / (area_i + g_area[img * CANDS + cand] - inter + 1e-9f);
            if (iou > 0.5f) live[cand] = -1.0f;
        }
        __syncthreads();
    }

    // outputs: boxes[2,100,4] | scores[2,100] | labels[2,100]  (all float)
    if (tid < DETN) {
        int   i = selI[tid];
        float s = selS[tid];
        bool keep = s > 0.05f;
        int k = i % 20 + 1;
        int r = img * S_PER + (i / 20);
        float4 bx = g_boxes4[r * NCLS + k];
        float* ob = out + ((size_t)img * DETN + tid) * 4;
        ob[0] = keep ? bx.x : 0.0f;
        ob[1] = keep ? bx.y : 0.0f;
        ob[2] = keep ? bx.z : 0.0f;
        ob[3] = keep ? bx.w : 0.0f;
        out[NIMG*DETN*4 + img*DETN + tid]              = keep ? s : 0.0f;
        out[NIMG*DETN*4 + NIMG*DETN + img*DETN + tid]  = keep ? (float)k : 0.0f;
    }
}

// ---------------- launch ----------------
extern "C" void kernel_launch(void* const* d_in, const int* in_sizes, int n_in,
                              void* d_out, int out_size)
{
    const float* features  = (const float*)d_in[0];
    const float* proposals = (const float*)d_in[1];
    const float* w1 = (const float*)d_in[2];
    const float* b1 = (const float*)d_in[3];
    const float* w2 = (const float*)d_in[4];
    const float* b2 = (const float*)d_in[5];
    const float* wc = (const float*)d_in[6];
    const float* bc = (const float*)d_in[7];
    const float* wb = (const float*)d_in[8];
    const float* bb = (const float*)d_in[9];
    const void*  imgp = d_in[10];
    float* out = (float*)d_out;

    void *p_feats, *p_h1, *p_h2;
    cudaGetSymbolAddress(&p_feats, g_feats);
    cudaGetSymbolAddress(&p_h1, g_h1);
    cudaGetSymbolAddress(&p_h2, g_h2);

    transpose_feat<<<dim3(79, 16, NIMG), dim3(32, 32)>>>(features);
    roi_align_kernel<<<R_TOT * 49, 128>>>(proposals);
    gemm_bias_relu<<<dim3(HIDN/64, R_TOT/64), 256>>>(
        (const float*)p_feats, w1, b1, (float*)p_h1, R_TOT, HIDN, D_FEAT, 1);
    gemm_bias_relu<<<dim3(HIDN/64, R_TOT/64), 256>>>(
        (const float*)p_h1, w2, b2, (float*)p_h2, R_TOT, HIDN, HIDN, 1);
    heads_kernel<<<R_TOT, 128>>>(wc, bc, wb, bb, proposals, imgp);
    nms_kernel<<<NIMG, 1024>>>(imgp, out);
}

// round 3
// speedup vs baseline: 1.6535x; 1.6535x over previous
#include <cuda_runtime.h>
#include <cuda_bf16.h>
#include <math.h>
#include <cstdint>

// ---------------- problem constants ----------------
#define NIMG   2
#define S_PER  512
#define R_TOT  1024          // NIMG * S_PER
#define C_FEAT 512
#define HW     2500          // 50*50
#define D_FEAT 25088         // C_FEAT * 49
#define HIDN   1024
#define NCLS   21
#define DETN   100
#define CANDS  10240         // S_PER * (NCLS-1)
#define LOG_MAX_F 4.135166556742356f

// ---------------- scratch (static device memory, no allocation) ----------------
__device__ float          g_featT[NIMG * HW * C_FEAT];            // [n][y][x][c]
__device__ __nv_bfloat16  g_Ahi[(size_t)R_TOT * D_FEAT];          // roi feats hi (K-major)
__device__ __nv_bfloat16  g_Alo[(size_t)R_TOT * D_FEAT];          // roi feats lo
__device__ __nv_bfloat16  g_Bhi[(size_t)HIDN * D_FEAT];           // w1^T permuted hi (K-major)
__device__ __nv_bfloat16  g_Blo[(size_t)HIDN * D_FEAT];           // w1^T permuted lo
__device__ float          g_h1[R_TOT * HIDN];
__device__ __nv_bfloat16  g_h1hi[R_TOT * HIDN];
__device__ __nv_bfloat16  g_h1lo[R_TOT * HIDN];
__device__ __nv_bfloat16  g_w2Thi[HIDN * HIDN];
__device__ __nv_bfloat16  g_w2Tlo[HIDN * HIDN];
__device__ float          g_h2[R_TOT * HIDN];
__device__ float          g_scores[R_TOT * NCLS];
__device__ float4         g_boxes4[R_TOT * NCLS];
__device__ float4         g_nb[NIMG * CANDS];
__device__ float          g_area[NIMG * CANDS];

// ---------------- helpers ----------------
__device__ __forceinline__ uint32_t smem_u32(const void* p) {
    uint32_t a;
    asm("{ .reg .u64 t; cvta.to.shared.u64 t, %1; cvt.u32.u64 %0, t; }" : "=r"(a) : "l"(p));
    return a;
}
__device__ __forceinline__ float read_img(const void* p) {
    int iv = *(const int*)p;
    if (iv > 0 && iv < 1000000) return (float)iv;
    float fv = *(const float*)p;
    if (fv >= 1.0f && fv <= 1.0e6f) return fv;
    double dv = *(const double*)p;
    return (float)dv;
}

#define LDSM4(r, a) \
    asm volatile("ldmatrix.sync.aligned.m8n8.x4.shared.b16 {%0,%1,%2,%3}, [%4];" \
        : "=r"((r)[0]), "=r"((r)[1]), "=r"((r)[2]), "=r"((r)[3]) : "r"(a))

#define MMA_BF16(c, a, b0, b1) \
    asm volatile("mma.sync.aligned.m16n8k16.row.col.f32.bf16.bf16.f32 " \
        "{%0,%1,%2,%3},{%4,%5,%6,%7},{%8,%9},{%0,%1,%2,%3};" \
        : "+f"((c)[0]), "+f"((c)[1]), "+f"((c)[2]), "+f"((c)[3]) \
        : "r"((a)[0]), "r"((a)[1]), "r"((a)[2]), "r"((a)[3]), "r"(b0), "r"(b1))

// ---------------- 1) transpose features [N,C,H,W] -> [N,H,W,C] ----------------
__global__ void transpose_feat(const float* __restrict__ in) {
    __shared__ float tile[32][33];
    int n  = blockIdx.z;
    int p0 = blockIdx.x * 32;
    int c0 = blockIdx.y * 32;
    int tx = threadIdx.x, ty = threadIdx.y;
    int p = p0 + tx, c = c0 + ty;
    if (p < HW) tile[ty][tx] = in[((size_t)(n * C_FEAT + c)) * HW + p];
    __syncthreads();
    p = p0 + ty; c = c0 + tx;
    if (p < HW) g_featT[((size_t)(n * HW + p)) * C_FEAT + c] = tile[tx][ty];
}

// ---------------- 2) ROI align -> split bf16 A, k' = pos*512 + c ----------------
__device__ __forceinline__ void split_store4(float v0, float v1, float v2, float v3, size_t base) {
    __nv_bfloat16 h0 = __float2bfloat16(v0), h1 = __float2bfloat16(v1),
                  h2 = __float2bfloat16(v2), h3 = __float2bfloat16(v3);
    float l0 = v0 - __bfloat162float(h0), l1 = v1 - __bfloat162float(h1),
          l2 = v2 - __bfloat162float(h2), l3 = v3 - __bfloat162float(h3);
    __nv_bfloat16 g0 = __float2bfloat16(l0), g1 = __float2bfloat16(l1),
                  g2 = __float2bfloat16(l2), g3 = __float2bfloat16(l3);
    uint2 uh, ul;
    uh.x = (uint32_t)__bfloat16_as_ushort(h0) | ((uint32_t)__bfloat16_as_ushort(h1) << 16);
    uh.y = (uint32_t)__bfloat16_as_ushort(h2) | ((uint32_t)__bfloat16_as_ushort(h3) << 16);
    ul.x = (uint32_t)__bfloat16_as_ushort(g0) | ((uint32_t)__bfloat16_as_ushort(g1) << 16);
    ul.y = (uint32_t)__bfloat16_as_ushort(g2) | ((uint32_t)__bfloat16_as_ushort(g3) << 16);
    *(uint2*)(g_Ahi + base) = uh;
    *(uint2*)(g_Alo + base) = ul;
}

__global__ void roi_align_kernel(const float* __restrict__ props) {
    int bid = blockIdx.x;
    int r   = bid / 49;
    int pos = bid % 49;
    int oy  = pos / 7, ox = pos % 7;
    int n   = r >> 9;
    const float SCALE = 1.0f / 16.0f;
    float b0 = props[r*4+0] * SCALE;
    float b1 = props[r*4+1] * SCALE;
    float b2 = props[r*4+2] * SCALE;
    float b3 = props[r*4+3] * SCALE;
    float rw = fmaxf(b2 - b0, 1.0f);
    float rh = fmaxf(b3 - b1, 1.0f);
    float bw = rw * (1.0f / 7.0f);
    float bh = rh * (1.0f / 7.0f);

    int c0 = threadIdx.x * 4;
    float4 acc = make_float4(0.f, 0.f, 0.f, 0.f);
    const float* base = g_featT + ((size_t)n * HW) * C_FEAT;

    #pragma unroll
    for (int sy = 0; sy < 2; sy++) {
        float gy = (float)oy + (sy ? 0.75f : 0.25f);
        float y  = b1 + gy * bh;
        bool  vy = (y > -1.0f) && (y < 50.0f);
        float yc = fminf(fmaxf(y, 0.0f), 49.0f);
        int   y0 = (int)floorf(yc);
        int   y1 = min(y0 + 1, 49);
        float ly = yc - (float)y0;
        #pragma unroll
        for (int sx = 0; sx < 2; sx++) {
            float gx = (float)ox + (sx ? 0.75f : 0.25f);
            float x  = b0 + gx * bw;
            bool  vx = (x > -1.0f) && (x < 50.0f);
            if (!(vy && vx)) continue;
            float xc = fminf(fmaxf(x, 0.0f), 49.0f);
            int   x0 = (int)floorf(xc);
            int   x1 = min(x0 + 1, 49);
            float lx = xc - (float)x0;
            const float4 f00 = *(const float4*)(base + ((size_t)(y0*50 + x0)) * C_FEAT + c0);
            const float4 f01 = *(const float4*)(base + ((size_t)(y0*50 + x1)) * C_FEAT + c0);
            const float4 f10 = *(const float4*)(base + ((size_t)(y1*50 + x0)) * C_FEAT + c0);
            const float4 f11 = *(const float4*)(base + ((size_t)(y1*50 + x1)) * C_FEAT + c0);
            float w00 = (1.0f-ly)*(1.0f-lx), w01 = (1.0f-ly)*lx;
            float w10 = ly*(1.0f-lx),        w11 = ly*lx;
            acc.x += f00.x*w00 + f01.x*w01 + f10.x*w10 + f11.x*w11;
            acc.y += f00.y*w00 + f01.y*w01 + f10.y*w10 + f11.y*w11;
            acc.z += f00.z*w00 + f01.z*w01 + f10.z*w10 + f11.z*w11;
            acc.w += f00.w*w00 + f01.w*w01 + f10.w*w10 + f11.w*w11;
        }
    }
    size_t obase = (size_t)r * D_FEAT + (size_t)pos * 512 + c0;
    split_store4(acc.x * 0.25f, acc.y * 0.25f, acc.z * 0.25f, acc.w * 0.25f, obase);
}

// ---------------- 3a) w1 -> B[n][k'=pos*512+c] bf16 hi/lo ----------------
__global__ void prep_w1(const float* __restrict__ w1) {
    __shared__ float t[32][33];
    int pos = blockIdx.x >> 4;            // 0..48
    int c0  = (blockIdx.x & 15) * 32;     // 0..480
    int n0  = blockIdx.y * 32;
    int j = threadIdx.x, i = threadIdx.y;
    t[i][j] = w1[((size_t)(c0 + i) * 49 + pos) * HIDN + n0 + j];
    __syncthreads();
    float v = t[j][i];
    __nv_bfloat16 h = __float2bfloat16(v);
    float l = v - __bfloat162float(h);
    size_t idx = (size_t)(n0 + i) * D_FEAT + (size_t)pos * 512 + c0 + j;
    g_Bhi[idx] = h;
    g_Blo[idx] = __float2bfloat16(l);
}

// ---------------- 3b) w2 -> w2T[n][k] bf16 hi/lo ----------------
__global__ void prep_w2(const float* __restrict__ w2) {
    __shared__ float t[32][33];
    int k0 = blockIdx.x * 32;
    int n0 = blockIdx.y * 32;
    int j = threadIdx.x, i = threadIdx.y;
    t[i][j] = w2[(size_t)(k0 + i) * HIDN + n0 + j];
    __syncthreads();
    float v = t[j][i];
    __nv_bfloat16 h = __float2bfloat16(v);
    float l = v - __bfloat162float(h);
    size_t idx = (size_t)(n0 + i) * HIDN + k0 + j;
    g_w2Thi[idx] = h;
    g_w2Tlo[idx] = __float2bfloat16(l);
}

// ---------------- 3c) split h1 fp32 -> bf16 hi/lo ----------------
__global__ void split_h1() {
    int idx = blockIdx.x * 1024 + threadIdx.x;
    float v = g_h1[idx];
    __nv_bfloat16 h = __float2bfloat16(v);
    g_h1hi[idx] = h;
    g_h1lo[idx] = __float2bfloat16(v - __bfloat162float(h));
}

// ---------------- 4) mma.sync bf16x3 GEMM: C = act((Ah+Al) @ (Bh+Bl)^T + bias) ----
// A: [1024][K] K-major, B: [N=1024][K] K-major. CTA tile 128(M)x64(N), BK=32.
// 8 warps: warp_m = wid&1 (64 rows), warp_n = wid>>1 (16 cols). Warp tile 64x16.
// SMEM matrices padded to stride 40 bf16 (80B) -> conflict-free ldmatrix.
#define SAB     40
#define AMAT_B  (128 * SAB * 2)   // 10240
#define BMAT_B  (64  * SAB * 2)   // 5120
#define OFF_AH  0
#define OFF_AL  AMAT_B
#define OFF_BH  (2 * AMAT_B)
#define OFF_BL  (2 * AMAT_B + BMAT_B)
#define BUF_B   (2 * AMAT_B + 2 * BMAT_B)   // 30720
#define GEMM_SMEM (2 * BUF_B)               // 61440

__global__ __launch_bounds__(256, 1) void gemm_bf16x3(
    const __nv_bfloat16* __restrict__ Ah, const __nv_bfloat16* __restrict__ Al,
    const __nv_bfloat16* __restrict__ Bh, const __nv_bfloat16* __restrict__ Bl,
    const float* __restrict__ bias, float* __restrict__ C, int K, int do_relu)
{
    extern __shared__ char smem[];
    const uint32_t sbase = smem_u32(smem);
    const int tid  = threadIdx.x;
    const int wid  = tid >> 5, lane = tid & 31;
    const int warp_m = wid & 1, warp_n = wid >> 1;
    const int row0 = blockIdx.y * 128;
    const int col0 = blockIdx.x * 64;
    const int NC = K >> 5;

    // global load mapping
    const int gr  = tid >> 1;            // A row 0..127
    const int gc8 = (tid & 1) * 16;      // A bf16 col base 0/16
    const int rb  = tid >> 2;            // B row 0..63
    const int cb8 = (tid & 3) * 8;       // B bf16 col base
    const uint4* pAh = (const uint4*)(Ah + (size_t)(row0 + gr) * K + gc8);
    const uint4* pAl = (const uint4*)(Al + (size_t)(row0 + gr) * K + gc8);
    const uint4* pBh = (const uint4*)(Bh + (size_t)(col0 + rb) * K + cb8);
    const uint4* pBl = (const uint4*)(Bl + (size_t)(col0 + rb) * K + cb8);

    const uint32_t sstA = (uint32_t)(gr * 80 + gc8 * 2);
    const uint32_t sstB = (uint32_t)(rb * 80 + cb8 * 2);

    // ldmatrix addresses (per-thread, within buffer)
    const uint32_t aAddr = sbase +
        (uint32_t)(((warp_m * 64 + (lane & 15)) * SAB + ((lane >> 4) << 3)) * 2);
    const uint32_t bAddr = sbase + OFF_BH +
        (uint32_t)(((warp_n * 16 + (lane & 7) + (((lane >> 4) & 1) << 3)) * SAB
                    + (((lane >> 3) & 1) << 3)) * 2);

    float acc[4][2][4];
    #pragma unroll
    for (int mt = 0; mt < 4; mt++)
        #pragma unroll
        for (int nt = 0; nt < 2; nt++)
            #pragma unroll
            for (int q = 0; q < 4; q++) acc[mt][nt][q] = 0.0f;

    uint4 vAh0, vAh1, vAl0, vAl1, vBh, vBl;

    // prologue: load chunk 0, store to buf 0
    {
        vAh0 = pAh[0]; vAh1 = pAh[1];
        vAl0 = pAl[0]; vAl1 = pAl[1];
        vBh  = pBh[0]; vBl  = pBl[0];
        char* s = smem;
        *(uint4*)(s + OFF_AH + sstA)      = vAh0;
        *(uint4*)(s + OFF_AH + sstA + 16) = vAh1;
        *(uint4*)(s + OFF_AL + sstA)      = vAl0;
        *(uint4*)(s + OFF_AL + sstA + 16) = vAl1;
        *(uint4*)(s + OFF_BH + sstB)      = vBh;
        *(uint4*)(s + OFF_BL + sstB)      = vBl;
    }
    __syncthreads();

    for (int c = 0; c < NC; c++) {
        // issue global loads for chunk c+1 (land during compute)
        if (c + 1 < NC) {
            int i4 = (c + 1) * 4;
            vAh0 = pAh[i4]; vAh1 = pAh[i4 + 1];
            vAl0 = pAl[i4]; vAl1 = pAl[i4 + 1];
            vBh  = pBh[i4]; vBl  = pBl[i4];
        }

        // compute on buffer c&1
        const uint32_t bufo = (uint32_t)(c & 1) * BUF_B;
        #pragma unroll
        for (int ks = 0; ks < 2; ks++) {
            const uint32_t ko = (uint32_t)ks * 32;   // 16 bf16 * 2B
            uint32_t ah[4][4], al[4][4], bh[4], bl[4];
            #pragma unroll
            for (int mt = 0; mt < 4; mt++) {
                LDSM4(ah[mt], aAddr + bufo + OFF_AH + (uint32_t)mt * 1280 + ko);
                LDSM4(al[mt], aAddr + bufo + OFF_AL + (uint32_t)mt * 1280 + ko);
            }
            LDSM4(bh, bAddr + bufo + ko);
            LDSM4(bl, bAddr + bufo + (OFF_BL - OFF_BH) + ko);

            #pragma unroll
            for (int mt = 0; mt < 4; mt++) {
                MMA_BF16(acc[mt][0], ah[mt], bh[0], bh[1]);
                MMA_BF16(acc[mt][1], ah[mt], bh[2], bh[3]);
            }
            #pragma unroll
            for (int mt = 0; mt < 4; mt++) {
                MMA_BF16(acc[mt][0], ah[mt], bl[0], bl[1]);
                MMA_BF16(acc[mt][1], ah[mt], bl[2], bl[3]);
            }
            #pragma unroll
            for (int mt = 0; mt < 4; mt++) {
                MMA_BF16(acc[mt][0], al[mt], bh[0], bh[1]);
                MMA_BF16(acc[mt][1], al[mt], bh[2], bh[3]);
            }
        }

        // store chunk c+1 into the other buffer
        if (c + 1 < NC) {
            char* s = smem + ((c + 1) & 1) * BUF_B;
            *(uint4*)(s + OFF_AH + sstA)      = vAh0;
            *(uint4*)(s + OFF_AH + sstA + 16) = vAh1;
            *(uint4*)(s + OFF_AL + sstA)      = vAl0;
            *(uint4*)(s + OFF_AL + sstA + 16) = vAl1;
            *(uint4*)(s + OFF_BH + sstB)      = vBh;
            *(uint4*)(s + OFF_BL + sstB)      = vBl;
        }
        __syncthreads();
    }

    // epilogue
    #pragma unroll
    for (int mt = 0; mt < 4; mt++) {
        int row = row0 + warp_m * 64 + mt * 16 + (lane >> 2);
        #pragma unroll
        for (int nt = 0; nt < 2; nt++) {
            int col = col0 + warp_n * 16 + nt * 8 + (lane & 3) * 2;
            float b0 = bias[col], b1 = bias[col + 1];
            float v0 = acc[mt][nt][0] + b0;
            float v1 = acc[mt][nt][1] + b1;
            float v2 = acc[mt][nt][2] + b0;
            float v3 = acc[mt][nt][3] + b1;
            if (do_relu) {
                v0 = fmaxf(v0, 0.f); v1 = fmaxf(v1, 0.f);
                v2 = fmaxf(v2, 0.f); v3 = fmaxf(v3, 0.f);
            }
            *(float2*)(C + (size_t)row * HIDN + col)       = make_float2(v0, v1);
            *(float2*)(C + (size_t)(row + 8) * HIDN + col) = make_float2(v2, v3);
        }
    }
}

// ---------------- 5) heads: cls/deltas GEMV + softmax + decode + clip ----------------
__global__ void heads_kernel(
    const float* __restrict__ wc, const float* __restrict__ bc,
    const float* __restrict__ wb, const float* __restrict__ bb,
    const float* __restrict__ props, const void* __restrict__ imgp)
{
    int r = blockIdx.x, tid = threadIdx.x;   // 128 threads
    __shared__ float h[HIDN];
    __shared__ float clsv[NCLS];
    __shared__ float dl[NCLS * 4];
    __shared__ float ex[NCLS];

    for (int i = tid; i < HIDN; i += 128) h[i] = g_h2[r * HIDN + i];
    __syncthreads();

    if (tid < NCLS) {
        float a0 = 0.f, a1 = 0.f, a2 = 0.f, a3 = 0.f;
        #pragma unroll 4
        for (int k = 0; k < HIDN; k += 4) {
            a0 += h[k+0] * wc[(k+0)*NCLS + tid];
            a1 += h[k+1] * wc[(k+1)*NCLS + tid];
            a2 += h[k+2] * wc[(k+2)*NCLS + tid];
            a3 += h[k+3] * wc[(k+3)*NCLS + tid];
        }
        clsv[tid] = (a0 + a1) + (a2 + a3) + bc[tid];
    } else if (tid < NCLS + 84) {
        int j = tid - NCLS;
        float a0 = 0.f, a1 = 0.f, a2 = 0.f, a3 = 0.f;
        #pragma unroll 4
        for (int k = 0; k < HIDN; k += 4) {
            a0 += h[k+0] * wb[(k+0)*84 + j];
            a1 += h[k+1] * wb[(k+1)*84 + j];
            a2 += h[k+2] * wb[(k+2)*84 + j];
            a3 += h[k+3] * wb[(k+3)*84 + j];
        }
        dl[j] = (a0 + a1) + (a2 + a3) + bb[j];
    }
    __syncthreads();

    if (tid < NCLS) {
        float m = clsv[0];
        #pragma unroll
        for (int i = 1; i < NCLS; i++) m = fmaxf(m, clsv[i]);
        ex[tid] = expf(clsv[tid] - m);
    }
    __syncthreads();

    if (tid < NCLS) {
        float s = 0.f;
        #pragma unroll
        for (int i = 0; i < NCLS; i++) s += ex[i];
        g_scores[r * NCLS + tid] = ex[tid] / s;

        float img = read_img(imgp);
        float p0 = props[r*4+0], p1 = props[r*4+1];
        float p2 = props[r*4+2], p3 = props[r*4+3];
        float pw  = p2 - p0, ph = p3 - p1;
        float pcx = p0 + 0.5f * pw, pcy = p1 + 0.5f * ph;
        float dx = dl[tid*4+0] / 10.0f;
        float dy = dl[tid*4+1] / 10.0f;
        float dw = fminf(dl[tid*4+2] / 5.0f, LOG_MAX_F);
        float dh = fminf(dl[tid*4+3] / 5.0f, LOG_MAX_F);
        float cx = dx * pw + pcx;
        float cy = dy * ph + pcy;
        float w  = expf(dw) * pw;
        float hh = expf(dh) * ph;
        float x1 = fminf(fmaxf(cx - 0.5f*w,  0.0f), img);
        float y1 = fminf(fmaxf(cy - 0.5f*hh, 0.0f), img);
        float x2 = fminf(fmaxf(cx + 0.5f*w,  0.0f), img);
        float y2 = fminf(fmaxf(cy + 0.5f*hh, 0.0f), img);
        g_boxes4[r * NCLS + tid] = make_float4(x1, y1, x2, y2);
    }
}

// ---------------- 6) exact sequential NMS, one block per image ----------------
__global__ __launch_bounds__(1024) void nms_kernel(const void* __restrict__ imgp,
                                                   float* __restrict__ out)
{
    int img = blockIdx.x;
    int tid = threadIdx.x;
    float IMG  = read_img(imgp);
    float offs = IMG + 1.0f;

    __shared__ float live[CANDS];
    __shared__ float wbest[32];
    __shared__ int   widx[32];
    __shared__ float selS[DETN];
    __shared__ int   selI[DETN];
    __shared__ int   s_si;

    #pragma unroll
    for (int g = 0; g < 10; g++) {
        int cand = g * 1024 + tid;
        int s = cand / 20, k = cand % 20 + 1;
        int r = img * S_PER + s;
        float sc  = g_scores[r * NCLS + k];
        float4 bx = g_boxes4[r * NCLS + k];
        float wv = bx.z - bx.x, hv = bx.w - bx.y;
        bool valid = (sc > 0.05f) && (wv >= 0.01f) && (hv >= 0.01f);
        live[cand] = valid ? sc : -1.0f;
        float o = (float)k * offs;
        float4 nb = make_float4(bx.x + o, bx.y + o, bx.z + o, bx.w + o);
        g_nb[img * CANDS + cand]   = nb;
        g_area[img * CANDS + cand] = (nb.z - nb.x) * (nb.w - nb.y);
    }
    __syncthreads();

    int lane = tid & 31, wid = tid >> 5;

    for (int it = 0; it < DETN; it++) {
        float best = -2.0f; int bidx = CANDS;
        #pragma unroll
        for (int g = 0; g < 10; g++) {
            int cand = g * 1024 + tid;
            float v = live[cand];
            if (v > best) { best = v; bidx = cand; }
        }
        #pragma unroll
        for (int o = 16; o; o >>= 1) {
            float ov = __shfl_down_sync(0xffffffffu, best, o);
            int   oi = __shfl_down_sync(0xffffffffu, bidx, o);
            if (ov > best || (ov == best && oi < bidx)) { best = ov; bidx = oi; }
        }
        if (lane == 0) { wbest[wid] = best; widx[wid] = bidx; }
        __syncthreads();
        if (wid == 0) {
            best = wbest[lane]; bidx = widx[lane];
            #pragma unroll
            for (int o = 16; o; o >>= 1) {
                float ov = __shfl_down_sync(0xffffffffu, best, o);
                int   oi = __shfl_down_sync(0xffffffffu, bidx, o);
                if (ov > best || (ov == best && oi < bidx)) { best = ov; bidx = oi; }
            }
            if (lane == 0) { s_si = bidx; selI[it] = bidx; selS[it] = best; }
        }
        __syncthreads();

        int si = s_si;
        float4 nbb = g_nb[img * CANDS + si];
        float area_i = (nbb.z - nbb.x) * (nbb.w - nbb.y);
        #pragma unroll
        for (int g = 0; g < 10; g++) {
            int cand = g * 1024 + tid;
            float4 nb = g_nb[img * CANDS + cand];
            float xx1 = fmaxf(nbb.x, nb.x);
            float yy1 = fmaxf(nbb.y, nb.y);
            float xx2 = fminf(nbb.z, nb.z);
            float yy2 = fminf(nbb.w, nb.w);
            float inter = fmaxf(xx2 - xx1, 0.0f) * fmaxf(yy2 - yy1, 0.0f);
            float iou = inter / (area_i + g_area[img * CANDS + cand] - inter + 1e-9f);
            if (iou > 0.5f) live[cand] = -1.0f;
        }
        __syncthreads();
    }

    if (tid < DETN) {
        int   i = selI[tid];
        float s = selS[tid];
        bool keep = s > 0.05f;
        int k = i % 20 + 1;
        int r = img * S_PER + (i / 20);
        float4 bx = g_boxes4[r * NCLS + k];
        float* ob = out + ((size_t)img * DETN + tid) * 4;
        ob[0] = keep ? bx.x : 0.0f;
        ob[1] = keep ? bx.y : 0.0f;
        ob[2] = keep ? bx.z : 0.0f;
        ob[3] = keep ? bx.w : 0.0f;
        out[NIMG*DETN*4 + img*DETN + tid]              = keep ? s : 0.0f;
        out[NIMG*DETN*4 + NIMG*DETN + img*DETN + tid]  = keep ? (float)k : 0.0f;
    }
}

// ---------------- launch ----------------
extern "C" void kernel_launch(void* const* d_in, const int* in_sizes, int n_in,
                              void* d_out, int out_size)
{
    const float* features  = (const float*)d_in[0];
    const float* proposals = (const float*)d_in[1];
    const float* w1 = (const float*)d_in[2];
    const float* b1 = (const float*)d_in[3];
    const float* w2 = (const float*)d_in[4];
    const float* b2 = (const float*)d_in[5];
    const float* wc = (const float*)d_in[6];
    const float* bc = (const float*)d_in[7];
    const float* wb = (const float*)d_in[8];
    const float* bb = (const float*)d_in[9];
    const void*  imgp = d_in[10];
    float* out = (float*)d_out;

    void *pAhi, *pAlo, *pBhi, *pBlo, *ph1, *ph1hi, *ph1lo, *pw2hi, *pw2lo, *ph2;
    cudaGetSymbolAddress(&pAhi,  g_Ahi);
    cudaGetSymbolAddress(&pAlo,  g_Alo);
    cudaGetSymbolAddress(&pBhi,  g_Bhi);
    cudaGetSymbolAddress(&pBlo,  g_Blo);
    cudaGetSymbolAddress(&ph1,   g_h1);
    cudaGetSymbolAddress(&ph1hi, g_h1hi);
    cudaGetSymbolAddress(&ph1lo, g_h1lo);
    cudaGetSymbolAddress(&pw2hi, g_w2Thi);
    cudaGetSymbolAddress(&pw2lo, g_w2Tlo);
    cudaGetSymbolAddress(&ph2,   g_h2);

    cudaFuncSetAttribute(gemm_bf16x3, cudaFuncAttributeMaxDynamicSharedMemorySize, GEMM_SMEM);

    transpose_feat<<<dim3(79, 16, NIMG), dim3(32, 32)>>>(features);
    prep_w1<<<dim3(49 * 16, 32), dim3(32, 32)>>>(w1);
    roi_align_kernel<<<R_TOT * 49, 128>>>(proposals);

    gemm_bf16x3<<<dim3(HIDN/64, R_TOT/128), 256, GEMM_SMEM>>>(
        (const __nv_bfloat16*)pAhi, (const __nv_bfloat16*)pAlo,
        (const __nv_bfloat16*)pBhi, (const __nv_bfloat16*)pBlo,
        b1, (float*)ph1, D_FEAT, 1);

    split_h1<<<1024, 1024>>>();
    prep_w2<<<dim3(32, 32), dim3(32, 32)>>>(w2);

    gemm_bf16x3<<<dim3(HIDN/64, R_TOT/128), 256, GEMM_SMEM>>>(
        (const __nv_bfloat16*)ph1hi, (const __nv_bfloat16*)ph1lo,
        (const __nv_bfloat16*)pw2hi, (const __nv_bfloat16*)pw2lo,
        b2, (float*)ph2, HIDN, 1);

    heads_kernel<<<R_TOT, 128>>>(wc, bc, wb, bb, proposals, imgp);
    nms_kernel<<<NIMG, 1024>>>(imgp, out);
}

// round 5
// speedup vs baseline: 2.1881x; 1.3233x over previous
#include <cuda_runtime.h>
#include <cuda_bf16.h>
#include <math.h>
#include <cstdint>

// ---------------- problem constants ----------------
#define NIMG   2
#define S_PER  512
#define R_TOT  1024
#define C_FEAT 512
#define HW     2500
#define D_FEAT 25088
#define HIDN   1024
#define NCLS   21
#define DETN   100
#define CANDS  10240
#define LOG_MAX_F 4.135166556742356f

// ---------------- scratch ----------------
__device__ float          g_featT[NIMG * HW * C_FEAT];
__device__ __nv_bfloat16  g_Ahi[(size_t)R_TOT * D_FEAT];
__device__ __nv_bfloat16  g_Alo[(size_t)R_TOT * D_FEAT];
__device__ __nv_bfloat16  g_Bhi[(size_t)HIDN * D_FEAT];
__device__ __nv_bfloat16  g_Blo[(size_t)HIDN * D_FEAT];
__device__ __nv_bfloat16  g_h1hi[R_TOT * HIDN];
__device__ __nv_bfloat16  g_h1lo[R_TOT * HIDN];
__device__ __nv_bfloat16  g_w2Thi[HIDN * HIDN];
__device__ __nv_bfloat16  g_w2Tlo[HIDN * HIDN];
__device__ float          g_h2[R_TOT * HIDN];
__device__ float          g_scores[R_TOT * NCLS];
__device__ float4         g_boxes4[R_TOT * NCLS];
__device__ int            g_map[NIMG * CANDS];

// ---------------- helpers ----------------
__device__ __forceinline__ uint32_t smem_u32(const void* p) {
    uint32_t a;
    asm("{ .reg .u64 t; cvta.to.shared.u64 t, %1; cvt.u32.u64 %0, t; }" : "=r"(a) : "l"(p));
    return a;
}
__device__ __forceinline__ float read_img(const void* p) {
    int iv = *(const int*)p;
    if (iv > 0 && iv < 1000000) return (float)iv;
    float fv = *(const float*)p;
    if (fv >= 1.0f && fv <= 1.0e6f) return fv;
    double dv = *(const double*)p;
    return (float)dv;
}

#define LDSM4(r, a) \
    asm volatile("ldmatrix.sync.aligned.m8n8.x4.shared.b16 {%0,%1,%2,%3}, [%4];" \
        : "=r"((r)[0]), "=r"((r)[1]), "=r"((r)[2]), "=r"((r)[3]) : "r"(a))

#define MMA_BF16(c, a, b0, b1) \
    asm volatile("mma.sync.aligned.m16n8k16.row.col.f32.bf16.bf16.f32 " \
        "{%0,%1,%2,%3},{%4,%5,%6,%7},{%8,%9},{%0,%1,%2,%3};" \
        : "+f"((c)[0]), "+f"((c)[1]), "+f"((c)[2]), "+f"((c)[3]) \
        : "r"((a)[0]), "r"((a)[1]), "r"((a)[2]), "r"((a)[3]), "r"(b0), "r"(b1))

#define CP16(dst, src) \
    asm volatile("cp.async.cg.shared.global [%0], [%1], 16;" :: "r"(dst), "l"(src))
#define CP_COMMIT() asm volatile("cp.async.commit_group;" ::: "memory")
#define CP_WAIT2()  asm volatile("cp.async.wait_group 2;" ::: "memory")

// ---------------- 1) transpose features [N,C,H,W] -> [N,H,W,C] ----------------
__global__ void transpose_feat(const float* __restrict__ in) {
    __shared__ float tile[32][33];
    int n  = blockIdx.z;
    int p0 = blockIdx.x * 32;
    int c0 = blockIdx.y * 32;
    int tx = threadIdx.x, ty = threadIdx.y;
    int p = p0 + tx, c = c0 + ty;
    if (p < HW) tile[ty][tx] = in[((size_t)(n * C_FEAT + c)) * HW + p];
    __syncthreads();
    p = p0 + ty; c = c0 + tx;
    if (p < HW) g_featT[((size_t)(n * HW + p)) * C_FEAT + c] = tile[tx][ty];
}

// ---------------- 2) ROI align -> split bf16 A ----------------
__device__ __forceinline__ void split_store4(float v0, float v1, float v2, float v3, size_t base) {
    __nv_bfloat16 h0 = __float2bfloat16(v0), h1 = __float2bfloat16(v1),
                  h2 = __float2bfloat16(v2), h3 = __float2bfloat16(v3);
    float l0 = v0 - __bfloat162float(h0), l1 = v1 - __bfloat162float(h1),
          l2 = v2 - __bfloat162float(h2), l3 = v3 - __bfloat162float(h3);
    __nv_bfloat16 g0 = __float2bfloat16(l0), g1 = __float2bfloat16(l1),
                  g2 = __float2bfloat16(l2), g3 = __float2bfloat16(l3);
    uint2 uh, ul;
    uh.x = (uint32_t)__bfloat16_as_ushort(h0) | ((uint32_t)__bfloat16_as_ushort(h1) << 16);
    uh.y = (uint32_t)__bfloat16_as_ushort(h2) | ((uint32_t)__bfloat16_as_ushort(h3) << 16);
    ul.x = (uint32_t)__bfloat16_as_ushort(g0) | ((uint32_t)__bfloat16_as_ushort(g1) << 16);
    ul.y = (uint32_t)__bfloat16_as_ushort(g2) | ((uint32_t)__bfloat16_as_ushort(g3) << 16);
    *(uint2*)(g_Ahi + base) = uh;
    *(uint2*)(g_Alo + base) = ul;
}

__global__ void roi_align_kernel(const float* __restrict__ props) {
    int bid = blockIdx.x;
    int r   = bid / 49;
    int pos = bid % 49;
    int oy  = pos / 7, ox = pos % 7;
    int n   = r >> 9;
    const float SCALE = 1.0f / 16.0f;
    float b0 = props[r*4+0] * SCALE;
    float b1 = props[r*4+1] * SCALE;
    float b2 = props[r*4+2] * SCALE;
    float b3 = props[r*4+3] * SCALE;
    float rw = fmaxf(b2 - b0, 1.0f);
    float rh = fmaxf(b3 - b1, 1.0f);
    float bw = rw * (1.0f / 7.0f);
    float bh = rh * (1.0f / 7.0f);

    int c0 = threadIdx.x * 4;
    float4 acc = make_float4(0.f, 0.f, 0.f, 0.f);
    const float* base = g_featT + ((size_t)n * HW) * C_FEAT;

    #pragma unroll
    for (int sy = 0; sy < 2; sy++) {
        float gy = (float)oy + (sy ? 0.75f : 0.25f);
        float y  = b1 + gy * bh;
        bool  vy = (y > -1.0f) && (y < 50.0f);
        float yc = fminf(fmaxf(y, 0.0f), 49.0f);
        int   y0 = (int)floorf(yc);
        int   y1 = min(y0 + 1, 49);
        float ly = yc - (float)y0;
        #pragma unroll
        for (int sx = 0; sx < 2; sx++) {
            float gx = (float)ox + (sx ? 0.75f : 0.25f);
            float x  = b0 + gx * bw;
            bool  vx = (x > -1.0f) && (x < 50.0f);
            if (!(vy && vx)) continue;
            float xc = fminf(fmaxf(x, 0.0f), 49.0f);
            int   x0 = (int)floorf(xc);
            int   x1 = min(x0 + 1, 49);
            float lx = xc - (float)x0;
            const float4 f00 = *(const float4*)(base + ((size_t)(y0*50 + x0)) * C_FEAT + c0);
            const float4 f01 = *(const float4*)(base + ((size_t)(y0*50 + x1)) * C_FEAT + c0);
            const float4 f10 = *(const float4*)(base + ((size_t)(y1*50 + x0)) * C_FEAT + c0);
            const float4 f11 = *(const float4*)(base + ((size_t)(y1*50 + x1)) * C_FEAT + c0);
            float w00 = (1.0f-ly)*(1.0f-lx), w01 = (1.0f-ly)*lx;
            float w10 = ly*(1.0f-lx),        w11 = ly*lx;
            acc.x += f00.x*w00 + f01.x*w01 + f10.x*w10 + f11.x*w11;
            acc.y += f00.y*w00 + f01.y*w01 + f10.y*w10 + f11.y*w11;
            acc.z += f00.z*w00 + f01.z*w01 + f10.z*w10 + f11.z*w11;
            acc.w += f00.w*w00 + f01.w*w01 + f10.w*w10 + f11.w*w11;
        }
    }
    size_t obase = (size_t)r * D_FEAT + (size_t)pos * 512 + c0;
    split_store4(acc.x * 0.25f, acc.y * 0.25f, acc.z * 0.25f, acc.w * 0.25f, obase);
}

// ---------------- 3a) w1 -> B[n][k'=pos*512+c] bf16 hi/lo ----------------
__global__ void prep_w1(const float* __restrict__ w1) {
    __shared__ float t[32][33];
    int pos = blockIdx.x >> 4;
    int c0  = (blockIdx.x & 15) * 32;
    int n0  = blockIdx.y * 32;
    int j = threadIdx.x, i = threadIdx.y;
    t[i][j] = w1[((size_t)(c0 + i) * 49 + pos) * HIDN + n0 + j];
    __syncthreads();
    float v = t[j][i];
    __nv_bfloat16 h = __float2bfloat16(v);
    float l = v - __bfloat162float(h);
    size_t idx = (size_t)(n0 + i) * D_FEAT + (size_t)pos * 512 + c0 + j;
    g_Bhi[idx] = h;
    g_Blo[idx] = __float2bfloat16(l);
}

// ---------------- 3b) w2 -> w2T[n][k] bf16 hi/lo ----------------
__global__ void prep_w2(const float* __restrict__ w2) {
    __shared__ float t[32][33];
    int k0 = blockIdx.x * 32;
    int n0 = blockIdx.y * 32;
    int j = threadIdx.x, i = threadIdx.y;
    t[i][j] = w2[(size_t)(k0 + i) * HIDN + n0 + j];
    __syncthreads();
    float v = t[j][i];
    __nv_bfloat16 h = __float2bfloat16(v);
    float l = v - __bfloat162float(h);
    size_t idx = (size_t)(n0 + i) * HIDN + k0 + j;
    g_w2Thi[idx] = h;
    g_w2Tlo[idx] = __float2bfloat16(l);
}

// ---------------- 4) cp.async 4-stage bf16x3 GEMM (64x64 tile, 4 warps) ----------
#define SAB      40
#define MAT_B    5120
#define STAGE_B  20480
#define NSTAGE   4
#define GEMM_SMEM (NSTAGE * STAGE_B)   // 81920

__global__ __launch_bounds__(128) void gemm_bf16x3(
    const __nv_bfloat16* __restrict__ Ah, const __nv_bfloat16* __restrict__ Al,
    const __nv_bfloat16* __restrict__ Bh, const __nv_bfloat16* __restrict__ Bl,
    const float* __restrict__ bias, float* __restrict__ Cf,
    __nv_bfloat16* __restrict__ Chi, __nv_bfloat16* __restrict__ Clo,
    int K, int mode)   // mode 1: relu + split bf16 store; mode 0: relu + fp32 store
{
    extern __shared__ char smem[];
    const uint32_t sbase = smem_u32(smem);
    const int tid  = threadIdx.x;
    const int wid  = tid >> 5, lane = tid & 31;
    const int warp_m = wid & 1, warp_n = wid >> 1;
    const int row0 = blockIdx.y * 64;
    const int col0 = blockIdx.x * 64;
    const int NC = K >> 5;
    const size_t Kb = (size_t)K * 2;

    const int rr  = tid >> 2;
    const int seg = tid & 3;
    const char* pAhB = (const char*)Ah + (size_t)row0 * Kb;
    const char* pAlB = (const char*)Al + (size_t)row0 * Kb;
    const char* pBhB = (const char*)Bh + (size_t)col0 * Kb;
    const char* pBlB = (const char*)Bl + (size_t)col0 * Kb;
    size_t gof[2];
    uint32_t sof[2];
    #pragma unroll
    for (int q = 0; q < 2; q++) {
        gof[q] = (size_t)(q * 32 + rr) * Kb + (size_t)seg * 16;
        sof[q] = (uint32_t)((q * 32 + rr) * 80 + seg * 16);
    }

    const uint32_t aAddr = sbase +
        (uint32_t)(((warp_m * 32 + (lane & 15)) * SAB + ((lane >> 4) << 3)) * 2);
    const uint32_t bAddr = sbase + 2 * MAT_B +
        (uint32_t)(((warp_n * 32 + (lane & 7) + (((lane >> 4) & 1) << 3)) * SAB
                    + (((lane >> 3) & 1) << 3)) * 2);

    float acc[2][4][4];
    #pragma unroll
    for (int mt = 0; mt < 2; mt++)
        #pragma unroll
        for (int nt = 0; nt < 4; nt++)
            #pragma unroll
            for (int q = 0; q < 4; q++) acc[mt][nt][q] = 0.0f;

    #pragma unroll
    for (int p = 0; p < 3; p++) {
        if (p < NC) {
            uint32_t sd = sbase + (uint32_t)p * STAGE_B;
            size_t gk = (size_t)p * 64;
            #pragma unroll
            for (int q = 0; q < 2; q++) {
                CP16(sd +             sof[q], pAhB + gof[q] + gk);
                CP16(sd +     MAT_B + sof[q], pAlB + gof[q] + gk);
                CP16(sd + 2 * MAT_B + sof[q], pBhB + gof[q] + gk);
                CP16(sd + 3 * MAT_B + sof[q], pBlB + gof[q] + gk);
            }
        }
        CP_COMMIT();
    }

    for (int c = 0; c < NC; c++) {
        CP_WAIT2();
        __syncthreads();

        if (c + 3 < NC) {
            uint32_t sd = sbase + (uint32_t)((c + 3) & 3) * STAGE_B;
            size_t gk = (size_t)(c + 3) * 64;
            #pragma unroll
            for (int q = 0; q < 2; q++) {
                CP16(sd +             sof[q], pAhB + gof[q] + gk);
                CP16(sd +     MAT_B + sof[q], pAlB + gof[q] + gk);
                CP16(sd + 2 * MAT_B + sof[q], pBhB + gof[q] + gk);
                CP16(sd + 3 * MAT_B + sof[q], pBlB + gof[q] + gk);
            }
        }
        CP_COMMIT();

        const uint32_t bufo = (uint32_t)(c & 3) * STAGE_B;
        #pragma unroll
        for (int ks = 0; ks < 2; ks++) {
            const uint32_t ko = bufo + (uint32_t)ks * 32;
            uint32_t ah[2][4], al[2][4], bh[2][4], bl[2][4];
            LDSM4(ah[0], aAddr + ko);
            LDSM4(ah[1], aAddr + ko + 1280);
            LDSM4(al[0], aAddr + ko + MAT_B);
            LDSM4(al[1], aAddr + ko + MAT_B + 1280);
            LDSM4(bh[0], bAddr + ko);
            LDSM4(bh[1], bAddr + ko + 1280);
            LDSM4(bl[0], bAddr + ko + MAT_B);
            LDSM4(bl[1], bAddr + ko + MAT_B + 1280);

            #pragma unroll
            for (int mt = 0; mt < 2; mt++)
                #pragma unroll
                for (int h = 0; h < 2; h++) {
                    MMA_BF16(acc[mt][2*h+0], ah[mt], bh[h][0], bh[h][1]);
                    MMA_BF16(acc[mt][2*h+1], ah[mt], bh[h][2], bh[h][3]);
                    MMA_BF16(acc[mt][2*h+0], ah[mt], bl[h][0], bl[h][1]);
                    MMA_BF16(acc[mt][2*h+1], ah[mt], bl[h][2], bl[h][3]);
                    MMA_BF16(acc[mt][2*h+0], al[mt], bh[h][0], bh[h][1]);
                    MMA_BF16(acc[mt][2*h+1], al[mt], bh[h][2], bh[h][3]);
                }
        }
    }

    // epilogue (ReLU in BOTH modes — reference applies relu to FC1 and FC2)
    #pragma unroll
    for (int mt = 0; mt < 2; mt++) {
        int row = row0 + warp_m * 32 + mt * 16 + (lane >> 2);
        #pragma unroll
        for (int nt = 0; nt < 4; nt++) {
            int col = col0 + warp_n * 32 + nt * 8 + (lane & 3) * 2;
            float b0 = bias[col], b1 = bias[col + 1];
            float v0 = fmaxf(acc[mt][nt][0] + b0, 0.0f);
            float v1 = fmaxf(acc[mt][nt][1] + b1, 0.0f);
            float v2 = fmaxf(acc[mt][nt][2] + b0, 0.0f);
            float v3 = fmaxf(acc[mt][nt][3] + b1, 0.0f);
            if (mode == 1) {
                __nv_bfloat16 h0 = __float2bfloat16(v0), h1 = __float2bfloat16(v1);
                __nv_bfloat16 h2 = __float2bfloat16(v2), h3 = __float2bfloat16(v3);
                __nv_bfloat16 l0 = __float2bfloat16(v0 - __bfloat162float(h0));
                __nv_bfloat16 l1 = __float2bfloat16(v1 - __bfloat162float(h1));
                __nv_bfloat16 l2 = __float2bfloat16(v2 - __bfloat162float(h2));
                __nv_bfloat16 l3 = __float2bfloat16(v3 - __bfloat162float(h3));
                size_t o1 = (size_t)row * HIDN + col;
                size_t o2 = (size_t)(row + 8) * HIDN + col;
                *(uint32_t*)(Chi + o1) = (uint32_t)__bfloat16_as_ushort(h0) |
                                         ((uint32_t)__bfloat16_as_ushort(h1) << 16);
                *(uint32_t*)(Clo + o1) = (uint32_t)__bfloat16_as_ushort(l0) |
                                         ((uint32_t)__bfloat16_as_ushort(l1) << 16);
                *(uint32_t*)(Chi + o2) = (uint32_t)__bfloat16_as_ushort(h2) |
                                         ((uint32_t)__bfloat16_as_ushort(h3) << 16);
                *(uint32_t*)(Clo + o2) = (uint32_t)__bfloat16_as_ushort(l2) |
                                         ((uint32_t)__bfloat16_as_ushort(l3) << 16);
            } else {
                *(float2*)(Cf + (size_t)row * HIDN + col)       = make_float2(v0, v1);
                *(float2*)(Cf + (size_t)(row + 8) * HIDN + col) = make_float2(v2, v3);
            }
        }
    }
}

// ---------------- 5) heads ----------------
__global__ void heads_kernel(
    const float* __restrict__ wc, const float* __restrict__ bc,
    const float* __restrict__ wb, const float* __restrict__ bb,
    const float* __restrict__ props, const void* __restrict__ imgp)
{
    int r = blockIdx.x, tid = threadIdx.x;
    __shared__ float h[HIDN];
    __shared__ float clsv[NCLS];
    __shared__ float dl[NCLS * 4];
    __shared__ float ex[NCLS];

    for (int i = tid; i < HIDN; i += 128) h[i] = g_h2[r * HIDN + i];
    __syncthreads();

    if (tid < NCLS) {
        float a0 = 0.f, a1 = 0.f, a2 = 0.f, a3 = 0.f;
        #pragma unroll 4
        for (int k = 0; k < HIDN; k += 4) {
            a0 += h[k+0] * wc[(k+0)*NCLS + tid];
            a1 += h[k+1] * wc[(k+1)*NCLS + tid];
            a2 += h[k+2] * wc[(k+2)*NCLS + tid];
            a3 += h[k+3] * wc[(k+3)*NCLS + tid];
        }
        clsv[tid] = (a0 + a1) + (a2 + a3) + bc[tid];
    } else if (tid < NCLS + 84) {
        int j = tid - NCLS;
        float a0 = 0.f, a1 = 0.f, a2 = 0.f, a3 = 0.f;
        #pragma unroll 4
        for (int k = 0; k < HIDN; k += 4) {
            a0 += h[k+0] * wb[(k+0)*84 + j];
            a1 += h[k+1] * wb[(k+1)*84 + j];
            a2 += h[k+2] * wb[(k+2)*84 + j];
            a3 += h[k+3] * wb[(k+3)*84 + j];
        }
        dl[j] = (a0 + a1) + (a2 + a3) + bb[j];
    }
    __syncthreads();

    if (tid < NCLS) {
        float m = clsv[0];
        #pragma unroll
        for (int i = 1; i < NCLS; i++) m = fmaxf(m, clsv[i]);
        ex[tid] = expf(clsv[tid] - m);
    }
    __syncthreads();

    if (tid < NCLS) {
        float s = 0.f;
        #pragma unroll
        for (int i = 0; i < NCLS; i++) s += ex[i];
        g_scores[r * NCLS + tid] = ex[tid] / s;

        float img = read_img(imgp);
        float p0 = props[r*4+0], p1 = props[r*4+1];
        float p2 = props[r*4+2], p3 = props[r*4+3];
        float pw  = p2 - p0, ph = p3 - p1;
        float pcx = p0 + 0.5f * pw, pcy = p1 + 0.5f * ph;
        float dx = dl[tid*4+0] / 10.0f;
        float dy = dl[tid*4+1] / 10.0f;
        float dw = fminf(dl[tid*4+2] / 5.0f, LOG_MAX_F);
        float dh = fminf(dl[tid*4+3] / 5.0f, LOG_MAX_F);
        float cx = dx * pw + pcx;
        float cy = dy * ph + pcy;
        float w  = expf(dw) * pw;
        float hh = expf(dh) * ph;
        float x1 = fminf(fmaxf(cx - 0.5f*w,  0.0f), img);
        float y1 = fminf(fmaxf(cy - 0.5f*hh, 0.0f), img);
        float x2 = fminf(fmaxf(cx + 0.5f*w,  0.0f), img);
        float y2 = fminf(fmaxf(cy + 0.5f*hh, 0.0f), img);
        g_boxes4[r * NCLS + tid] = make_float4(x1, y1, x2, y2);
    }
}

// ---------------- 6) NMS: compaction + smem-resident loop ----------------
#define NMS_SMEM (CANDS * 20)
__global__ __launch_bounds__(1024) void nms_kernel(const void* __restrict__ imgp,
                                                   float* __restrict__ out)
{
    extern __shared__ char nsm[];
    float4* s_nb   = (float4*)nsm;
    float*  s_live = (float*)(nsm + CANDS * 16);

    __shared__ float wbest[32];
    __shared__ int   widx[32];
    __shared__ float selS[DETN];
    __shared__ int   selI[DETN];
    __shared__ int   wsum[32];
    __shared__ int   s_si;

    int img = blockIdx.x;
    int tid = threadIdx.x;
    int lane = tid & 31, wid = tid >> 5;
    float IMG  = read_img(imgp);
    float offs = IMG + 1.0f;

    int base = tid * 10;
    uint32_t flags = 0;
    int cnt = 0;
    #pragma unroll
    for (int j = 0; j < 10; j++) {
        int cand = base + j;
        int s = cand / 20, k = cand % 20 + 1;
        int r = img * S_PER + s;
        float sc  = g_scores[r * NCLS + k];
        float4 bx = g_boxes4[r * NCLS + k];
        bool valid = (sc > 0.05f) && (bx.z - bx.x >= 0.01f) && (bx.w - bx.y >= 0.01f);
        if (valid) { flags |= (1u << j); cnt++; }
    }
    int inc = cnt;
    #pragma unroll
    for (int o = 1; o < 32; o <<= 1) {
        int u = __shfl_up_sync(0xffffffffu, inc, o);
        if (lane >= o) inc += u;
    }
    if (lane == 31) wsum[wid] = inc;
    __syncthreads();
    if (wid == 0) {
        int v = wsum[lane];
        #pragma unroll
        for (int o = 1; o < 32; o <<= 1) {
            int u = __shfl_up_sync(0xffffffffu, v, o);
            if (lane >= o) v += u;
        }
        wsum[lane] = v;
    }
    __syncthreads();
    int off = inc - cnt + (wid ? wsum[wid - 1] : 0);
    const int V = wsum[31];

    #pragma unroll
    for (int j = 0; j < 10; j++) {
        if (flags & (1u << j)) {
            int cand = base + j;
            int s = cand / 20, k = cand % 20 + 1;
            int r = img * S_PER + s;
            float sc  = g_scores[r * NCLS + k];
            float4 bx = g_boxes4[r * NCLS + k];
            float o = (float)k * offs;
            s_live[off] = sc;
            s_nb[off]   = make_float4(bx.x + o, bx.y + o, bx.z + o, bx.w + o);
            g_map[img * CANDS + off] = cand;
            off++;
        }
    }
    __syncthreads();

    if (V > 0) {
        for (int it = 0; it < DETN; it++) {
            float best = -2.0f; int bidx = V;
            for (int i = tid; i < V; i += 1024) {
                float v = s_live[i];
                if (v > best) { best = v; bidx = i; }
            }
            #pragma unroll
            for (int o = 16; o; o >>= 1) {
                float ov = __shfl_down_sync(0xffffffffu, best, o);
                int   oi = __shfl_down_sync(0xffffffffu, bidx, o);
                if (ov > best || (ov == best && oi < bidx)) { best = ov; bidx = oi; }
            }
            if (lane == 0) { wbest[wid] = best; widx[wid] = bidx; }
            __syncthreads();
            if (wid == 0) {
                best = wbest[lane]; bidx = widx[lane];
                #pragma unroll
                for (int o = 16; o; o >>= 1) {
                    float ov = __shfl_down_sync(0xffffffffu, best, o);
                    int   oi = __shfl_down_sync(0xffffffffu, bidx, o);
                    if (ov > best || (ov == best && oi < bidx)) { best = ov; bidx = oi; }
                }
                if (lane == 0) { s_si = bidx; selI[it] = bidx; selS[it] = best; }
            }
            __syncthreads();

            float4 nbb = s_nb[s_si];
            float area_i = (nbb.z - nbb.x) * (nbb.w - nbb.y);
            for (int i = tid; i < V; i += 1024) {
                float4 nb = s_nb[i];
                float xx1 = fmaxf(nbb.x, nb.x);
                float yy1 = fmaxf(nbb.y, nb.y);
                float xx2 = fminf(nbb.z, nb.z);
                float yy2 = fminf(nbb.w, nb.w);
                float inter = fmaxf(xx2 - xx1, 0.0f) * fmaxf(yy2 - yy1, 0.0f);
                float areaj = (nb.z - nb.x) * (nb.w - nb.y);
                float iou = inter / (area_i + areaj - inter + 1e-9f);
                if (iou > 0.5f) s_live[i] = -1.0f;
            }
            __syncthreads();
        }
    }

    if (tid < DETN) {
        float s = (V > 0) ? selS[tid] : -1.0f;
        bool keep = s > 0.05f;
        float* ob = out + ((size_t)img * DETN + tid) * 4;
        if (keep) {
            int orig = g_map[img * CANDS + selI[tid]];
            int k = orig % 20 + 1;
            int r = img * S_PER + (orig / 20);
            float4 bx = g_boxes4[r * NCLS + k];
            ob[0] = bx.x; ob[1] = bx.y; ob[2] = bx.z; ob[3] = bx.w;
            out[NIMG*DETN*4 + img*DETN + tid]             = s;
            out[NIMG*DETN*4 + NIMG*DETN + img*DETN + tid] = (float)k;
        } else {
            ob[0] = 0.f; ob[1] = 0.f; ob[2] = 0.f; ob[3] = 0.f;
            out[NIMG*DETN*4 + img*DETN + tid]             = 0.f;
            out[NIMG*DETN*4 + NIMG*DETN + img*DETN + tid] = 0.f;
        }
    }
}

// ---------------- launch ----------------
extern "C" void kernel_launch(void* const* d_in, const int* in_sizes, int n_in,
                              void* d_out, int out_size)
{
    const float* features  = (const float*)d_in[0];
    const float* proposals = (const float*)d_in[1];
    const float* w1 = (const float*)d_in[2];
    const float* b1 = (const float*)d_in[3];
    const float* w2 = (const float*)d_in[4];
    const float* b2 = (const float*)d_in[5];
    const float* wc = (const float*)d_in[6];
    const float* bc = (const float*)d_in[7];
    const float* wb = (const float*)d_in[8];
    const float* bb = (const float*)d_in[9];
    const void*  imgp = d_in[10];
    float* out = (float*)d_out;

    void *pAhi, *pAlo, *pBhi, *pBlo, *ph1hi, *ph1lo, *pw2hi, *pw2lo, *ph2;
    cudaGetSymbolAddress(&pAhi,  g_Ahi);
    cudaGetSymbolAddress(&pAlo,  g_Alo);
    cudaGetSymbolAddress(&pBhi,  g_Bhi);
    cudaGetSymbolAddress(&pBlo,  g_Blo);
    cudaGetSymbolAddress(&ph1hi, g_h1hi);
    cudaGetSymbolAddress(&ph1lo, g_h1lo);
    cudaGetSymbolAddress(&pw2hi, g_w2Thi);
    cudaGetSymbolAddress(&pw2lo, g_w2Tlo);
    cudaGetSymbolAddress(&ph2,   g_h2);

    cudaFuncSetAttribute(gemm_bf16x3, cudaFuncAttributeMaxDynamicSharedMemorySize, GEMM_SMEM);
    cudaFuncSetAttribute(nms_kernel,  cudaFuncAttributeMaxDynamicSharedMemorySize, NMS_SMEM);

    transpose_feat<<<dim3(79, 16, NIMG), dim3(32, 32)>>>(features);
    prep_w1<<<dim3(49 * 16, 32), dim3(32, 32)>>>(w1);
    roi_align_kernel<<<R_TOT * 49, 128>>>(proposals);

    gemm_bf16x3<<<dim3(HIDN/64, R_TOT/64), 128, GEMM_SMEM>>>(
        (const __nv_bfloat16*)pAhi, (const __nv_bfloat16*)pAlo,
        (const __nv_bfloat16*)pBhi, (const __nv_bfloat16*)pBlo,
        b1, nullptr, (__nv_bfloat16*)ph1hi, (__nv_bfloat16*)ph1lo, D_FEAT, 1);

    prep_w2<<<dim3(32, 32), dim3(32, 32)>>>(w2);

    gemm_bf16x3<<<dim3(HIDN/64, R_TOT/64), 128, GEMM_SMEM>>>(
        (const __nv_bfloat16*)ph1hi, (const __nv_bfloat16*)ph1lo,
        (const __nv_bfloat16*)pw2hi, (const __nv_bfloat16*)pw2lo,
        b2, (float*)ph2, nullptr, nullptr, HIDN, 0);

    heads_kernel<<<R_TOT, 128>>>(wc, bc, wb, bb, proposals, imgp);
    nms_kernel<<<NIMG, 1024, NMS_SMEM>>>(imgp, out);
}